// round 11
// baseline (speedup 1.0000x reference)
#include <cuda_runtime.h>
#include <cuda_bf16.h>
#include <math.h>

// ---------------- problem constants ----------------
#define NC 80
#define REG_MAX 16
#define NO 144            // 4*REG_MAX + NC
#define A_TOT 8400        // 6400 + 1600 + 400
#define PRE_TOPK 1000
#define MAX_DET 100
#define B_MAX 32
#define NBINS 4096

// ---------------- scratch (device globals; no allocation allowed) ----------------
__device__ float  g_conf[B_MAX * A_TOT];
__device__ int    g_cls [B_MAX * A_TOT];
__device__ float4 g_box [B_MAX * A_TOT];

// ---------------- helpers ----------------
__device__ __forceinline__ unsigned f2key(float v) {
    unsigned u = __float_as_uint(v);
    return (u & 0x80000000u) ? ~u : (u | 0x80000000u);
}
__device__ __forceinline__ float key2f(unsigned k) {
    unsigned u = (k & 0x80000000u) ? (k & 0x7FFFFFFFu) : ~k;
    return __uint_as_float(u);
}
__device__ __forceinline__ int val2bin(float v) {
    float t = (v - 0.25f) * (4096.0f / 0.75f);
    int b = (int)t;
    if (b < 0) b = 0;
    if (b > NBINS - 1) b = NBINS - 1;
    return b;
}
__device__ __forceinline__ unsigned long long packkey(float v, int idx) {
    return ((unsigned long long)f2key(v) << 32) |
           (unsigned long long)(0xFFFFFFFFu - (unsigned)idx);
}

// ---------------- kernel 1: decode (bit-identical to passing rounds) ----------------
__global__ void __launch_bounds__(256) decode_kernel(const float* __restrict__ p3,
                                                     const float* __restrict__ p4,
                                                     const float* __restrict__ p5)
{
    int a = blockIdx.x * blockDim.x + threadIdx.x;
    int b = blockIdx.y;
    if (a >= A_TOT) return;

    const float* src;
    int w, local;
    float stride;
    if (a < 6400)      { src = p3; w = 80; stride = 8.f;  local = a; }
    else if (a < 8000) { src = p4; w = 40; stride = 16.f; local = a - 6400; }
    else               { src = p5; w = 20; stride = 32.f; local = a - 8000; }

    int plane = w * w;
    int y = local / w;
    int x = local - y * w;
    const float* base = src + (size_t)b * NO * plane + y * w + x;

    float best = -INFINITY;
    int bi = 0;
    #pragma unroll 4
    for (int c = 0; c < NC; ++c) {
        float v = base[(4 * REG_MAX + c) * plane];
        if (v > best) { best = v; bi = c; }
    }
    float conf = 1.0f / (1.0f + expf(-best));

    float d[4];
    #pragma unroll
    for (int k = 0; k < 4; ++k) {
        float lg[REG_MAX];
        float m = -INFINITY;
        #pragma unroll
        for (int r = 0; r < REG_MAX; ++r) {
            lg[r] = base[(k * REG_MAX + r) * plane];
            m = fmaxf(m, lg[r]);
        }
        float s = 0.f, dot = 0.f;
        #pragma unroll
        for (int r = 0; r < REG_MAX; ++r) {
            float e = expf(lg[r] - m);
            s += e;
            dot += e * (float)r;
        }
        d[k] = dot / s;
    }

    float xa = (float)x + 0.5f, ya = (float)y + 0.5f;
    float x1g = xa - d[0], y1g = ya - d[1];
    float x2g = xa + d[2], y2g = ya + d[3];
    float cx = (x1g + x2g) * 0.5f * stride;
    float cy = (y1g + y2g) * 0.5f * stride;
    float bw = (x2g - x1g) * stride;
    float bh = (y2g - y1g) * stride;

    int o = b * A_TOT + a;
    g_conf[o] = (conf > 0.25f) ? conf : -1.0f;
    g_cls[o]  = bi;
    g_box[o] = make_float4(cx - bw * 0.5f, cy - bh * 0.5f,
                           cx + bw * 0.5f, cy + bh * 0.5f);
}

// ---------------- kernel 2: fused topk + frontier NMS + output ----------------
// smem layout (37120 B), phase-aliased:
//   phase 1 (select):  hist@0 [4096 int], blist@20480 [1024 u64], cand@28672 [1024 u64]
//   phase 2 (NMS):     bx1@0, by1@4096, bx2@8192, by2@12288, cf@16384, scls@20480
//                      aw@24576 [32 u32], dets@24704 [100 int]
//   always:            ctr@36864 [8 int], ws@36896 [32 int]
#define SM_BYTES 37120

__global__ void __launch_bounds__(1024) fused_post_kernel(float* __restrict__ out, int B)
{
    __shared__ __align__(16) char sm[SM_BYTES];
    int*                hist  = (int*)sm;
    unsigned long long* blist = (unsigned long long*)(sm + 20480);
    unsigned long long* cand  = (unsigned long long*)(sm + 28672);
    float* bx1 = (float*)(sm + 0);
    float* by1 = (float*)(sm + 4096);
    float* bx2 = (float*)(sm + 8192);
    float* by2 = (float*)(sm + 12288);
    float* cf  = (float*)(sm + 16384);
    int*   scls = (int*)(sm + 20480);
    unsigned* aw  = (unsigned*)(sm + 24576);
    int*   dets  = (int*)(sm + 24704);
    int*   ctr = (int*)(sm + 36864);
    int*   ws  = ctr + 8;

    int b    = blockIdx.x;
    int tid  = threadIdx.x;
    int lane = tid & 31;
    int wid  = tid >> 5;
    const float* conf = g_conf + b * A_TOT;

    // ---------- phase 1a: histogram ----------
    for (int t = tid; t < NBINS; t += 1024) hist[t] = 0;
    if (tid == 0) { ctr[0] = 0; ctr[1] = 0; ctr[2] = 0; ctr[3] = 0; ctr[5] = 0; }
    __syncthreads();
    for (int t = tid; t < A_TOT; t += 1024)
        atomicAdd(&hist[val2bin(conf[t])], 1);
    __syncthreads();

    // ---------- phase 1b: suffix scan ----------
    int g = hist[4 * tid] + hist[4 * tid + 1] + hist[4 * tid + 2] + hist[4 * tid + 3];
    int s = g;
    #pragma unroll
    for (int o = 1; o < 32; o <<= 1) {
        int v = __shfl_down_sync(0xFFFFFFFFu, s, o);
        if (lane + o < 32) s += v;
    }
    if (lane == 0) ws[wid] = s;
    __syncthreads();
    if (wid == 0) {
        int v = ws[lane];
        int t2 = v;
        #pragma unroll
        for (int o = 1; o < 32; o <<= 1) {
            int u = __shfl_down_sync(0xFFFFFFFFu, t2, o);
            if (lane + o < 32) t2 += u;
        }
        ws[lane] = t2 - v;
    }
    __syncthreads();
    {
        int above = ws[wid] + (s - g);
        #pragma unroll
        for (int k = 3; k >= 0; --k) {
            int bin = 4 * tid + k;
            int cum = above + hist[bin];
            if (cum >= PRE_TOPK && above < PRE_TOPK) { ctr[2] = bin; ctr[3] = above; }
            above = cum;
        }
    }
    __syncthreads();
    int cross   = ctr[2];
    int greater = ctr[3];
    int needed  = PRE_TOPK - greater;

    // ---------- phase 1c: compaction ----------
    for (int t = tid; t < 9216; t += 1024) {
        bool in = t < A_TOT;
        float v = in ? conf[t] : 0.f;
        int bin = in ? val2bin(v) : -1;
        bool pg = in && (bin > cross);
        unsigned mg = __ballot_sync(0xFFFFFFFFu, pg);
        if (mg) {
            int leader = __ffs(mg) - 1;
            int base = 0;
            if (lane == leader) base = atomicAdd(&ctr[0], __popc(mg));
            base = __shfl_sync(0xFFFFFFFFu, base, leader);
            if (pg) cand[base + __popc(mg & ((1u << lane) - 1u))] = packkey(v, t);
        }
        bool pe = in && (bin == cross);
        unsigned me = __ballot_sync(0xFFFFFFFFu, pe);
        if (me) {
            int leader = __ffs(me) - 1;
            int base = 0;
            if (lane == leader) base = atomicAdd(&ctr[1], __popc(me));
            base = __shfl_sync(0xFFFFFFFFu, base, leader);
            if (pe) {
                int pos = base + __popc(me & ((1u << lane) - 1u));
                if (pos < 1024) blist[pos] = packkey(v, t);
            }
        }
    }
    __syncthreads();

    // ---------- phase 1d: boundary rank selection ----------
    int m = ctr[1];
    if (needed > 0) {
        if (m <= 1024) {
            for (int e = tid; e < m; e += 1024) {
                unsigned long long ke = blist[e];
                int rank = 0;
                for (int j = 0; j < m; ++j) rank += (blist[j] > ke) ? 1 : 0;
                if (rank < needed) cand[atomicAdd(&ctr[0], 1)] = ke;
            }
        } else {
            for (int i = tid; i < A_TOT; i += 1024) {
                float v = conf[i];
                if (val2bin(v) != cross) continue;
                unsigned long long ki = packkey(v, i);
                int rank = 0;
                for (int j = 0; j < A_TOT; ++j) {
                    float vj = conf[j];
                    if (val2bin(vj) != cross) continue;
                    rank += (packkey(vj, j) > ki) ? 1 : 0;
                }
                if (rank < needed) cand[atomicAdd(&ctr[0], 1)] = ki;
            }
        }
    }
    __syncthreads();
    if (tid >= PRE_TOPK) cand[tid] = 0ull;
    __syncthreads();

    // ---------- phase 1e: rank-scatter into smem (hist/blist dead) ----------
    if (tid < PRE_TOPK) {
        unsigned long long ke = cand[tid];
        int rank = 0;
        for (int j = 0; j < PRE_TOPK; ++j)
            rank += (cand[j] > ke) ? 1 : 0;     // broadcast smem reads
        int si = (int)(0xFFFFFFFFu - (unsigned)ke);
        float4 bb = g_box[b * A_TOT + si];
        cf[rank]  = key2f((unsigned)(ke >> 32));
        bx1[rank] = bb.x; by1[rank] = bb.y;
        bx2[rank] = bb.z; by2[rank] = bb.w;
        scls[rank] = g_cls[b * A_TOT + si];
    }
    __syncthreads();

    // ---------- phase 2: frontier NMS (<=100 steps, exact IoU) ----------
    float x1 = 0.f, y1 = 0.f, x2 = 0.f, y2 = 0.f, mycf = -1.f;
    if (tid < PRE_TOPK) {
        x1 = bx1[tid]; y1 = by1[tid]; x2 = bx2[tid]; y2 = by2[tid];
        mycf = cf[tid];
    }
    bool alive = (tid < PRE_TOPK) && (mycf > 0.f);
    float areaB = (x2 - x1) * (y2 - y1);

    {
        unsigned bal = __ballot_sync(0xFFFFFFFFu, alive);
        if (lane == 0) aw[wid] = bal;
    }
    __syncthreads();

    for (;;) {
        if (wid == 0) {
            unsigned w = aw[lane];
            unsigned nz = __ballot_sync(0xFFFFFFFFu, w != 0);
            int cur = -1;
            if (nz) {
                int fw = __ffs(nz) - 1;
                unsigned word = __shfl_sync(0xFFFFFFFFu, w, fw);
                cur = fw * 32 + __ffs(word) - 1;
            }
            if (lane == 0) {
                ctr[6] = cur;
                if (cur >= 0) { dets[ctr[5]] = cur; ctr[5] = ctr[5] + 1; }
            }
        }
        __syncthreads();
        int cur = ctr[6];
        int nd  = ctr[5];
        if (cur < 0) break;

        float ax1 = bx1[cur], ay1 = by1[cur], ax2 = bx2[cur], ay2 = by2[cur];
        if (alive) {
            if (tid == cur) alive = false;
            else if (tid > cur) {
                float areaA = (ax2 - ax1) * (ay2 - ay1);
                float ix1 = fmaxf(ax1, x1);
                float iy1 = fmaxf(ay1, y1);
                float ix2 = fminf(ax2, x2);
                float iy2 = fminf(ay2, y2);
                float iw = fmaxf(ix2 - ix1, 0.f);
                float ih = fmaxf(iy2 - iy1, 0.f);
                float inter = iw * ih;
                float iou = inter / (areaA + areaB - inter + 1e-7f);
                if (iou > 0.45f) alive = false;
            }
        }
        unsigned nb = __ballot_sync(0xFFFFFFFFu, alive);
        if (lane == 0) aw[wid] = nb;
        if (nd >= MAX_DET) break;
        __syncthreads();
    }
    __syncthreads();

    int ndet = ctr[5];
    if (ndet > MAX_DET) ndet = MAX_DET;

    // ---------- phase 3: output ----------
    // layout: [num_dets (B)] [boxes (B*100*4)] [scores (B*100)] [classes (B*100)]
    float* o_num = out;
    float* o_box = out + B;
    float* o_sc  = out + B + B * MAX_DET * 4;
    float* o_cl  = out + B + B * MAX_DET * 5;

    if (tid < MAX_DET) {
        bool valid = tid < ndet;
        int sp = valid ? dets[tid] : 0;
        o_sc[b * MAX_DET + tid] = valid ? cf[sp] : 0.f;
        float4 bb = valid ? make_float4(bx1[sp], by1[sp], bx2[sp], by2[sp])
                          : make_float4(0.f, 0.f, 0.f, 0.f);
        ((float4*)o_box)[b * MAX_DET + tid] = bb;
        o_cl[b * MAX_DET + tid] = valid ? (float)scls[sp] : 0.f;
    }
    if (tid == 0) o_num[b] = (float)ndet;
}

// ---------------- launcher ----------------
extern "C" void kernel_launch(void* const* d_in, const int* in_sizes, int n_in,
                              void* d_out, int out_size)
{
    const float* p3 = (const float*)d_in[0];
    const float* p4 = (const float*)d_in[1];
    const float* p5 = (const float*)d_in[2];
    int B = in_sizes[0] / (NO * 80 * 80);
    if (B > B_MAX) B = B_MAX;

    dim3 g1((A_TOT + 255) / 256, B);
    decode_kernel<<<g1, 256>>>(p3, p4, p5);
    fused_post_kernel<<<B, 1024>>>((float*)d_out, B);
}